// round 6
// baseline (speedup 1.0000x reference)
#include <cuda_runtime.h>
#include <cstdint>

#define B_   32
#define N_   64
#define GS_  80
#define NG_  6400
#define NA_  3
#define TK_  3
#define NC_  80

// output layout (floats), reference return order: bboxes, scores, anc, fg
#define BB_OFF  0
#define SC_OFF  (B_*NA_*NG_*4)                 // 2,457,600
#define ANC_OFF (SC_OFF + B_*NA_*NG_*NC_)      // 51,609,600
#define FG_OFF  (ANC_OFF + 6)                  // 51,609,606

#define SLAB4   (NG_ * (NC_ / 4))              // 128000 float4 per (b,a) score slab

// scratch (device globals — no allocation allowed)
__device__ int g_asgn[B_ * NG_];   // packed: tgt(8) | label<<8 | fg<<16

typedef unsigned long long ull;

// ------- Kernel 1: fused topk + claim scatter + conflict resolve (per batch) -------
// One block per batch, 256 threads.
// Phase 1: threads 0..63 compute top-3 nearest cells for their GT. Candidates
//   provably lie in the 7x7 window around floor(cx),floor(cy) (3rd-best L1
//   dist <= 2.0 everywhere incl. borders). key=(distbits<<32)|g min-select
//   reproduces jax top_k's lowest-index tie-break exactly.
// Phase 2: 192 claims scattered into smem via atomicAdd ((1<<16)+t packing).
// Phase 3: per-cell O(1) resolve; rare multi-claim cells argmin over 64 GTs.
__global__ void setup_kernel(const float* __restrict__ gt_cxys,
                             const float* __restrict__ mask_gt,
                             const int*   __restrict__ gt_labels) {
    const int b   = blockIdx.x;
    const int tid = threadIdx.x;

    __shared__ int   claims[NG_];            // (count<<16) + sum_of_t
    __shared__ float scx[N_], scy[N_];
    __shared__ int   st[N_ * TK_];
    __shared__ int   slab[N_];

    for (int g = tid; g < NG_; g += 256) claims[g] = 0;

    if (tid < N_) {
        const float cx = gt_cxys[(b * N_ + tid) * 2 + 0];
        const float cy = gt_cxys[(b * N_ + tid) * 2 + 1];
        scx[tid]  = cx;
        scy[tid]  = cy;
        slab[tid] = gt_labels[b * N_ + tid];

        int xs = (int)floorf(cx) - 3; xs = xs < 0 ? 0 : (xs > GS_ - 7 ? GS_ - 7 : xs);
        int ys = (int)floorf(cy) - 3; ys = ys < 0 ? 0 : (ys > GS_ - 7 ? GS_ - 7 : ys);

        ull k0 = ~0ull, k1 = ~0ull, k2 = ~0ull;
#pragma unroll
        for (int dy = 0; dy < 7; dy++) {
            const int y = ys + dy;
            const float ady = fabsf(((float)y + 0.5f) - cy);
#pragma unroll
            for (int dx = 0; dx < 7; dx++) {
                const int x = xs + dx;
                const float d = fabsf(((float)x + 0.5f) - cx) + ady;
                const ull key = ((ull)__float_as_uint(d) << 32) | (unsigned)(y * GS_ + x);
                if (key < k2) {
                    if (key < k0)      { k2 = k1; k1 = k0; k0 = key; }
                    else if (key < k1) { k2 = k1; k1 = key; }
                    else               { k2 = key; }
                }
            }
        }
        st[tid * TK_ + 0] = (int)(k0 & 0xffffffffu);
        st[tid * TK_ + 1] = (int)(k1 & 0xffffffffu);
        st[tid * TK_ + 2] = (int)(k2 & 0xffffffffu);
    }
    __syncthreads();

    if (tid < N_ * TK_) {
        const int t = tid / TK_;
        const int g = st[tid];
        const float v = mask_gt[((size_t)(b * N_ + t)) * NG_ + g];
        if (v != 0.0f) atomicAdd(&claims[g], (1 << 16) + t);
    }
    __syncthreads();

    for (int g = tid; g < NG_; g += 256) {
        const int c   = claims[g];
        const int cnt = c >> 16;
        int tgt, fg;
        if (cnt == 0)      { tgt = 0;           fg = 0; }
        else if (cnt == 1) { tgt = c & 0xffff;  fg = 1; }
        else {
            // conflict: nearest GT over ALL 64 (ties -> lowest t); keep only
            // if that GT itself claims g (topk) AND is valid
            const float fx = (float)(g % GS_) + 0.5f;
            const float fy = (float)(g / GS_) + 0.5f;
            ull best = ~0ull;
            for (int t = 0; t < N_; t++) {
                const float d = fabsf(fx - scx[t]) + fabsf(fy - scy[t]);
                const ull key = ((ull)__float_as_uint(d) << 32) | (unsigned)t;
                best = key < best ? key : best;
            }
            const int mgt = (int)(best & 0xffffffffu);
            const bool mem = (st[mgt*3] == g) | (st[mgt*3+1] == g) | (st[mgt*3+2] == g);
            const bool has = mem && (mask_gt[((size_t)(b * N_ + mgt)) * NG_ + g] != 0.0f);
            fg  = has ? 1 : 0;
            tgt = has ? mgt : 0;
        }
        g_asgn[b * NG_ + g] = tgt | (slab[tgt] << 8) | (fg << 16);
    }
}

// ------- Kernel 2: fused output writer. grid (127, B_), blockIdx.y = b -------
// Scores and bboxes are IDENTICAL across the NA=3 anchor dim (only fg differs),
// so each value is computed once and stored three times (slabs 2MB apart, each
// store fully coalesced).
//   blockIdx.x < 125   : score blocks. 4 float4 one-hots computed, 12 stored.
//   blockIdx.x 125/126 : bbox float4 (x3), per-anchor fg, anc copy (half NG_ each).
#define SC_U 4
__global__ void write_kernel(const float* __restrict__ anc_wh,
                             const float* __restrict__ grid,
                             const float* __restrict__ gt_cxys,
                             const float* __restrict__ gt_whs,
                             float* __restrict__ out) {
    const int b   = blockIdx.y;
    const int tid = threadIdx.x;
    const int* __restrict__ asg = g_asgn + b * NG_;

    if (blockIdx.x < 125) {
        float4* __restrict__ dst =
            reinterpret_cast<float4*>(out + SC_OFF) + (size_t)b * (NA_ * SLAB4);

        int i = blockIdx.x * (256 * SC_U) + tid;   // float4 idx within one slab
#pragma unroll
        for (int u = 0; u < SC_U; u++, i += 256) {
            const int g  = i / (NC_ / 4);          // const-divisor: mulhi
            const int c  = (i - g * (NC_ / 4)) * 4;
            const int lab = (asg[g] >> 8) & 0xff;
            float4 v;
            v.x = (c + 0 == lab) ? 1.0f : 0.0f;
            v.y = (c + 1 == lab) ? 1.0f : 0.0f;
            v.z = (c + 2 == lab) ? 1.0f : 0.0f;
            v.w = (c + 3 == lab) ? 1.0f : 0.0f;
            dst[i]             = v;
            dst[i + SLAB4]     = v;
            dst[i + 2 * SLAB4] = v;
        }
    } else {
        // anchors to registers (6 floats)
        const float aw0 = anc_wh[0], ah0 = anc_wh[1];
        const float aw1 = anc_wh[2], ah1 = anc_wh[3];
        const float aw2 = anc_wh[4], ah2 = anc_wh[5];

        const int g0 = (blockIdx.x - 125) * (NG_ / 2);   // 0 or 3200
        float4* __restrict__ bb = reinterpret_cast<float4*>(out + BB_OFF);
        for (int g = g0 + tid; g < g0 + NG_ / 2; g += 256) {
            const int packed = asg[g];
            const int tgt = packed & 0xff;
            const int fg  = (packed >> 16) & 1;

            const float cx = gt_cxys[(b * N_ + tgt) * 2 + 0];
            const float cy = gt_cxys[(b * N_ + tgt) * 2 + 1];
            const float w  = gt_whs [(b * N_ + tgt) * 2 + 0];
            const float h  = gt_whs [(b * N_ + tgt) * 2 + 1];
            const float gx = grid[g * 2 + 0];
            const float gy = grid[g * 2 + 1];

            const int idx0 = (b * NA_) * NG_ + g;
            const float4 bv = make_float4(cx - gx, cy - gy, w, h);
            bb[idx0]           = bv;
            bb[idx0 + NG_]     = bv;
            bb[idx0 + 2 * NG_] = bv;

            float r1, r2, m;
            r1 = w / aw0; r2 = h / ah0;
            m  = fmaxf(fmaxf(r1, 1.0f / r1), fmaxf(r2, 1.0f / r2));
            out[FG_OFF + idx0]           = (fg && (m < 4.0f)) ? 1.0f : 0.0f;
            r1 = w / aw1; r2 = h / ah1;
            m  = fmaxf(fmaxf(r1, 1.0f / r1), fmaxf(r2, 1.0f / r2));
            out[FG_OFF + idx0 + NG_]     = (fg && (m < 4.0f)) ? 1.0f : 0.0f;
            r1 = w / aw2; r2 = h / ah2;
            m  = fmaxf(fmaxf(r1, 1.0f / r1), fmaxf(r2, 1.0f / r2));
            out[FG_OFF + idx0 + 2 * NG_] = (fg && (m < 4.0f)) ? 1.0f : 0.0f;
        }
        if (b == 0 && blockIdx.x == 125 && tid < 6) out[ANC_OFF + tid] = anc_wh[tid];
    }
}

extern "C" void kernel_launch(void* const* d_in, const int* in_sizes, int n_in,
                              void* d_out, int out_size) {
    const float* anc_wh    = (const float*)d_in[0];
    const float* grid      = (const float*)d_in[1];
    const int*   gt_labels = (const int*)  d_in[2];
    const float* gt_cxys   = (const float*)d_in[3];
    const float* gt_whs    = (const float*)d_in[4];
    const float* mask_gt   = (const float*)d_in[5];
    float* out = (float*)d_out;

    setup_kernel<<<B_, 256>>>(gt_cxys, mask_gt, gt_labels);

    dim3 gw(127, B_);
    write_kernel<<<gw, 256>>>(anc_wh, grid, gt_cxys, gt_whs, out);
}

// round 8
// speedup vs baseline: 1.1069x; 1.1069x over previous
#include <cuda_runtime.h>
#include <cstdint>

#define B_   32
#define N_   64
#define GS_  80
#define NG_  6400
#define NA_  3
#define TK_  3
#define NC_  80

// output layout (floats), reference return order: bboxes, scores, anc, fg
#define BB_OFF  0
#define SC_OFF  (B_*NA_*NG_*4)                 // 2,457,600
#define ANC_OFF (SC_OFF + B_*NA_*NG_*NC_)      // 51,609,600
#define FG_OFF  (ANC_OFF + 6)                  // 51,609,606

// scratch (device globals — no allocation allowed)
__device__ int g_asgn[B_ * NG_];   // packed: tgt(8) | label<<8 | fg<<16

typedef unsigned long long ull;

// ------- Kernel 1: fused topk + claim scatter + conflict resolve (per batch) -------
// One block per batch, 256 threads.
// Phase 1: threads 0..63 compute top-3 nearest cells for their GT. Candidates
//   provably lie in the 7x7 window around floor(cx),floor(cy) (3rd-best L1
//   dist <= 2.0 everywhere incl. borders). key=(distbits<<32)|g min-select
//   reproduces jax top_k's lowest-index tie-break exactly.
// Phase 2: 192 claims scattered into smem via atomicAdd ((1<<16)+t packing).
// Phase 3: per-cell O(1) resolve; rare multi-claim cells argmin over 64 GTs.
__global__ void setup_kernel(const float* __restrict__ gt_cxys,
                             const float* __restrict__ mask_gt,
                             const int*   __restrict__ gt_labels) {
    const int b   = blockIdx.x;
    const int tid = threadIdx.x;

    __shared__ int   claims[NG_];            // (count<<16) + sum_of_t
    __shared__ float scx[N_], scy[N_];
    __shared__ int   st[N_ * TK_];
    __shared__ int   slab[N_];

    for (int g = tid; g < NG_; g += 256) claims[g] = 0;

    if (tid < N_) {
        const float cx = gt_cxys[(b * N_ + tid) * 2 + 0];
        const float cy = gt_cxys[(b * N_ + tid) * 2 + 1];
        scx[tid]  = cx;
        scy[tid]  = cy;
        slab[tid] = gt_labels[b * N_ + tid];

        int xs = (int)floorf(cx) - 3; xs = xs < 0 ? 0 : (xs > GS_ - 7 ? GS_ - 7 : xs);
        int ys = (int)floorf(cy) - 3; ys = ys < 0 ? 0 : (ys > GS_ - 7 ? GS_ - 7 : ys);

        ull k0 = ~0ull, k1 = ~0ull, k2 = ~0ull;
#pragma unroll
        for (int dy = 0; dy < 7; dy++) {
            const int y = ys + dy;
            const float ady = fabsf(((float)y + 0.5f) - cy);
#pragma unroll
            for (int dx = 0; dx < 7; dx++) {
                const int x = xs + dx;
                const float d = fabsf(((float)x + 0.5f) - cx) + ady;
                const ull key = ((ull)__float_as_uint(d) << 32) | (unsigned)(y * GS_ + x);
                if (key < k2) {
                    if (key < k0)      { k2 = k1; k1 = k0; k0 = key; }
                    else if (key < k1) { k2 = k1; k1 = key; }
                    else               { k2 = key; }
                }
            }
        }
        st[tid * TK_ + 0] = (int)(k0 & 0xffffffffu);
        st[tid * TK_ + 1] = (int)(k1 & 0xffffffffu);
        st[tid * TK_ + 2] = (int)(k2 & 0xffffffffu);
    }
    __syncthreads();

    if (tid < N_ * TK_) {
        const int t = tid / TK_;
        const int g = st[tid];
        const float v = mask_gt[((size_t)(b * N_ + t)) * NG_ + g];
        if (v != 0.0f) atomicAdd(&claims[g], (1 << 16) + t);
    }
    __syncthreads();

    for (int g = tid; g < NG_; g += 256) {
        const int c   = claims[g];
        const int cnt = c >> 16;
        int tgt, fg;
        if (cnt == 0)      { tgt = 0;           fg = 0; }
        else if (cnt == 1) { tgt = c & 0xffff;  fg = 1; }
        else {
            // conflict: nearest GT over ALL 64 (ties -> lowest t); keep only
            // if that GT itself claims g (topk) AND is valid
            const float fx = (float)(g % GS_) + 0.5f;
            const float fy = (float)(g / GS_) + 0.5f;
            ull best = ~0ull;
            for (int t = 0; t < N_; t++) {
                const float d = fabsf(fx - scx[t]) + fabsf(fy - scy[t]);
                const ull key = ((ull)__float_as_uint(d) << 32) | (unsigned)t;
                best = key < best ? key : best;
            }
            const int mgt = (int)(best & 0xffffffffu);
            const bool mem = (st[mgt*3] == g) | (st[mgt*3+1] == g) | (st[mgt*3+2] == g);
            const bool has = mem && (mask_gt[((size_t)(b * N_ + mgt)) * NG_ + g] != 0.0f);
            fg  = has ? 1 : 0;
            tgt = has ? mgt : 0;
        }
        g_asgn[b * NG_ + g] = tgt | (slab[tgt] << 8) | (fg << 16);
    }
}

// ------- Kernel 2: bboxes (float4), fg mask, anc copy. grid (25, 96) -------
__global__ void box_kernel(const float* __restrict__ anc_wh,
                           const float* __restrict__ grid,
                           const float* __restrict__ gt_cxys,
                           const float* __restrict__ gt_whs,
                           float* __restrict__ out) {
    const int g  = blockIdx.x * blockDim.x + threadIdx.x;   // < NG_
    const int ba = blockIdx.y;                              // b*NA + a
    const int b  = ba / NA_;
    const int a  = ba - b * NA_;
    const int idx = ba * NG_ + g;

    const int packed = g_asgn[b * NG_ + g];
    const int tgt = packed & 0xff;
    const int fg  = (packed >> 16) & 1;

    const float cx = gt_cxys[(b * N_ + tgt) * 2 + 0];
    const float cy = gt_cxys[(b * N_ + tgt) * 2 + 1];
    const float w  = gt_whs [(b * N_ + tgt) * 2 + 0];
    const float h  = gt_whs [(b * N_ + tgt) * 2 + 1];
    const float gx = grid[g * 2 + 0];
    const float gy = grid[g * 2 + 1];

    reinterpret_cast<float4*>(out + BB_OFF)[idx] = make_float4(cx - gx, cy - gy, w, h);

    const float aw = anc_wh[a * 2 + 0], ah = anc_wh[a * 2 + 1];
    const float r1 = w / aw, r2 = h / ah;
    const float m  = fmaxf(fmaxf(r1, 1.0f / r1), fmaxf(r2, 1.0f / r2));
    out[FG_OFF + idx] = (fg && (m < 4.0f)) ? 1.0f : 0.0f;

    if (ba == 0 && g < 6) out[ANC_OFF + g] = anc_wh[g];
}

// ------- Kernel 3: one-hot scores. grid (125, 96), blockIdx.y = (b,a) slab -------
// Each thread writes 4 float4s block-strided (coalesced); 32-bit const-divisor
// index math only. Plain stores (no __stcs — hurt in R2; no replication — hurt in R6).
#define SC_U 4
__global__ void score_kernel(float* __restrict__ out) {
    const int ba  = blockIdx.y;            // 0..95
    const int b   = ba / NA_;
    const int* __restrict__ asg = g_asgn + b * NG_;
    float4* __restrict__ dst =
        reinterpret_cast<float4*>(out + SC_OFF) + (size_t)ba * (NG_ * (NC_ / 4));

    int i = blockIdx.x * (256 * SC_U) + threadIdx.x;   // float4 idx in slab
#pragma unroll
    for (int u = 0; u < SC_U; u++, i += 256) {
        const int g  = i / (NC_ / 4);                  // const div: mulhi
        const int c  = (i - g * (NC_ / 4)) * 4;
        const int lab = (asg[g] >> 8) & 0xff;
        float4 v;
        v.x = (c + 0 == lab) ? 1.0f : 0.0f;
        v.y = (c + 1 == lab) ? 1.0f : 0.0f;
        v.z = (c + 2 == lab) ? 1.0f : 0.0f;
        v.w = (c + 3 == lab) ? 1.0f : 0.0f;
        dst[i] = v;
    }
}

extern "C" void kernel_launch(void* const* d_in, const int* in_sizes, int n_in,
                              void* d_out, int out_size) {
    const float* anc_wh    = (const float*)d_in[0];
    const float* grid      = (const float*)d_in[1];
    const int*   gt_labels = (const int*)  d_in[2];
    const float* gt_cxys   = (const float*)d_in[3];
    const float* gt_whs    = (const float*)d_in[4];
    const float* mask_gt   = (const float*)d_in[5];
    float* out = (float*)d_out;

    setup_kernel<<<B_, 256>>>(gt_cxys, mask_gt, gt_labels);

    dim3 gbox(NG_ / 256, B_ * NA_);
    box_kernel<<<gbox, 256>>>(anc_wh, grid, gt_cxys, gt_whs, out);

    dim3 gsc(NG_ * (NC_ / 4) / (256 * SC_U), B_ * NA_);   // (125, 96)
    score_kernel<<<gsc, 256>>>(out);
}

// round 9
// speedup vs baseline: 1.2253x; 1.1070x over previous
#include <cuda_runtime.h>
#include <cstdint>

#define B_   32
#define N_   64
#define GS_  80
#define NG_  6400
#define NA_  3
#define TK_  3
#define NC_  80

// output layout (floats), reference return order: bboxes, scores, anc, fg
#define BB_OFF  0
#define SC_OFF  (B_*NA_*NG_*4)                 // 2,457,600
#define ANC_OFF (SC_OFF + B_*NA_*NG_*NC_)      // 51,609,600
#define FG_OFF  (ANC_OFF + 6)                  // 51,609,606

// scratch (device globals — no allocation allowed)
__device__ int g_asgn[B_ * NG_];   // packed: tgt(8) | label<<8 | fg<<16

typedef unsigned long long ull;

// ------- Kernel 1: fused topk + claim scatter + conflict resolve (per batch) -------
// One block per batch, 256 threads.
// Phase 1: threads 0..63 compute top-3 nearest cells for their GT. Candidates
//   provably lie in the 7x7 window around floor(cx),floor(cy) (3rd-best L1
//   dist <= 2.0 everywhere incl. borders). key=(distbits<<32)|g min-select
//   reproduces jax top_k's lowest-index tie-break exactly.
// Phase 2: 192 claims scattered into smem via atomicAdd ((1<<16)+t packing).
// Phase 3: per-cell O(1) resolve; rare multi-claim cells argmin over 64 GTs.
__global__ void setup_kernel(const float* __restrict__ gt_cxys,
                             const float* __restrict__ mask_gt,
                             const int*   __restrict__ gt_labels) {
    const int b   = blockIdx.x;
    const int tid = threadIdx.x;

    __shared__ int   claims[NG_];            // (count<<16) + sum_of_t
    __shared__ float scx[N_], scy[N_];
    __shared__ int   st[N_ * TK_];
    __shared__ int   slab[N_];

    for (int g = tid; g < NG_; g += 256) claims[g] = 0;

    if (tid < N_) {
        const float cx = gt_cxys[(b * N_ + tid) * 2 + 0];
        const float cy = gt_cxys[(b * N_ + tid) * 2 + 1];
        scx[tid]  = cx;
        scy[tid]  = cy;
        slab[tid] = gt_labels[b * N_ + tid];

        int xs = (int)floorf(cx) - 3; xs = xs < 0 ? 0 : (xs > GS_ - 7 ? GS_ - 7 : xs);
        int ys = (int)floorf(cy) - 3; ys = ys < 0 ? 0 : (ys > GS_ - 7 ? GS_ - 7 : ys);

        ull k0 = ~0ull, k1 = ~0ull, k2 = ~0ull;
#pragma unroll
        for (int dy = 0; dy < 7; dy++) {
            const int y = ys + dy;
            const float ady = fabsf(((float)y + 0.5f) - cy);
#pragma unroll
            for (int dx = 0; dx < 7; dx++) {
                const int x = xs + dx;
                const float d = fabsf(((float)x + 0.5f) - cx) + ady;
                const ull key = ((ull)__float_as_uint(d) << 32) | (unsigned)(y * GS_ + x);
                if (key < k2) {
                    if (key < k0)      { k2 = k1; k1 = k0; k0 = key; }
                    else if (key < k1) { k2 = k1; k1 = key; }
                    else               { k2 = key; }
                }
            }
        }
        st[tid * TK_ + 0] = (int)(k0 & 0xffffffffu);
        st[tid * TK_ + 1] = (int)(k1 & 0xffffffffu);
        st[tid * TK_ + 2] = (int)(k2 & 0xffffffffu);
    }
    __syncthreads();

    if (tid < N_ * TK_) {
        const int t = tid / TK_;
        const int g = st[tid];
        const float v = mask_gt[((size_t)(b * N_ + t)) * NG_ + g];
        if (v != 0.0f) atomicAdd(&claims[g], (1 << 16) + t);
    }
    __syncthreads();

    for (int g = tid; g < NG_; g += 256) {
        const int c   = claims[g];
        const int cnt = c >> 16;
        int tgt, fg;
        if (cnt == 0)      { tgt = 0;           fg = 0; }
        else if (cnt == 1) { tgt = c & 0xffff;  fg = 1; }
        else {
            // conflict: nearest GT over ALL 64 (ties -> lowest t); keep only
            // if that GT itself claims g (topk) AND is valid
            const float fx = (float)(g % GS_) + 0.5f;
            const float fy = (float)(g / GS_) + 0.5f;
            ull best = ~0ull;
            for (int t = 0; t < N_; t++) {
                const float d = fabsf(fx - scx[t]) + fabsf(fy - scy[t]);
                const ull key = ((ull)__float_as_uint(d) << 32) | (unsigned)t;
                best = key < best ? key : best;
            }
            const int mgt = (int)(best & 0xffffffffu);
            const bool mem = (st[mgt*3] == g) | (st[mgt*3+1] == g) | (st[mgt*3+2] == g);
            const bool has = mem && (mask_gt[((size_t)(b * N_ + mgt)) * NG_ + g] != 0.0f);
            fg  = has ? 1 : 0;
            tgt = has ? mgt : 0;
        }
        g_asgn[b * NG_ + g] = tgt | (slab[tgt] << 8) | (fg << 16);
    }
}

// ------- Kernel 2: bboxes (float4), fg mask, anc copy (R2 version, verbatim) -------
__global__ void box_kernel(const float* __restrict__ anc_wh,
                           const float* __restrict__ grid,
                           const float* __restrict__ gt_cxys,
                           const float* __restrict__ gt_whs,
                           float* __restrict__ out) {
    const int idx = blockIdx.x * blockDim.x + threadIdx.x;   // B*NA*NG = 614400
    if (idx >= B_ * NA_ * NG_) return;
    const int g = idx % NG_;
    const int a = (idx / NG_) % NA_;
    const int b = idx / (NG_ * NA_);

    const int packed = g_asgn[b * NG_ + g];
    const int tgt = packed & 0xff;
    const int fg  = (packed >> 16) & 1;

    const float cx = gt_cxys[(b * N_ + tgt) * 2 + 0];
    const float cy = gt_cxys[(b * N_ + tgt) * 2 + 1];
    const float w  = gt_whs [(b * N_ + tgt) * 2 + 0];
    const float h  = gt_whs [(b * N_ + tgt) * 2 + 1];
    const float gx = grid[g * 2 + 0];
    const float gy = grid[g * 2 + 1];

    __stcs(reinterpret_cast<float4*>(out + BB_OFF) + idx,
           make_float4(cx - gx, cy - gy, w, h));

    const float aw = anc_wh[a * 2 + 0], ah = anc_wh[a * 2 + 1];
    const float r1 = w / aw, r2 = h / ah;
    const float m  = fmaxf(fmaxf(r1, 1.0f / r1), fmaxf(r2, 1.0f / r2));
    out[FG_OFF + idx] = (fg && (m < 4.0f)) ? 1.0f : 0.0f;

    if (idx < 6) out[ANC_OFF + idx] = anc_wh[idx];
}

// ------- Kernel 3: one-hot scores, one float4 per thread (R2 version, verbatim) -------
__global__ void score_kernel(float* __restrict__ out) {
    const long long idx = (long long)blockIdx.x * blockDim.x + threadIdx.x;
    const long long total = (long long)B_ * NA_ * NG_ * (NC_ / 4);     // 12,288,000
    if (idx >= total) return;

    const int c4 = (int)(idx % (NC_ / 4));
    const long long q = idx / (NC_ / 4);        // (b,a,g) flat
    const int g = (int)(q % NG_);
    const int b = (int)(q / (NG_ * NA_));

    const int lab = (g_asgn[b * NG_ + g] >> 8) & 0xff;
    const int c = c4 * 4;
    float4 v;
    v.x = (c + 0 == lab) ? 1.0f : 0.0f;
    v.y = (c + 1 == lab) ? 1.0f : 0.0f;
    v.z = (c + 2 == lab) ? 1.0f : 0.0f;
    v.w = (c + 3 == lab) ? 1.0f : 0.0f;
    __stcs(reinterpret_cast<float4*>(out + SC_OFF) + idx, v);
}

extern "C" void kernel_launch(void* const* d_in, const int* in_sizes, int n_in,
                              void* d_out, int out_size) {
    const float* anc_wh    = (const float*)d_in[0];
    const float* grid      = (const float*)d_in[1];
    const int*   gt_labels = (const int*)  d_in[2];
    const float* gt_cxys   = (const float*)d_in[3];
    const float* gt_whs    = (const float*)d_in[4];
    const float* mask_gt   = (const float*)d_in[5];
    float* out = (float*)d_out;

    setup_kernel<<<B_, 256>>>(gt_cxys, mask_gt, gt_labels);

    const int nbox = B_ * NA_ * NG_;
    box_kernel<<<(nbox + 255) / 256, 256>>>(anc_wh, grid, gt_cxys, gt_whs, out);

    const long long nsc = (long long)B_ * NA_ * NG_ * (NC_ / 4);
    score_kernel<<<(unsigned)((nsc + 255) / 256), 256>>>(out);
}